// round 9
// baseline (speedup 1.0000x reference)
#include <cuda_runtime.h>
#include <cstdint>

typedef unsigned long long ull;

// Problem constants (fixed by setup_inputs)
#define NB 4
#define CC 128
#define HH 160
#define WW 320
#define DD 48

#define WT   128            // w-tile per CTA
#define RT   (WT + 48)      // right tile width incl. disparity halo = 176
#define CHS  16             // channels per pipeline stage
#define NSTG (CC / CHS)     // 8 stages
#define NTHR 128            // 4 warps: one per SMSP, each owns 12 disparities

#define STAGE_FLOATS (CHS * (WT + RT))     // 4864 floats = 19456 B
#define SMEM_FLOATS  (2 * STAGE_FLOATS)    // double buffer: 38912 B

__device__ __forceinline__ uint32_t smem_u32(const void* p) {
    return (uint32_t)__cvta_generic_to_shared(p);
}
// 16B async copy, global->shared, zero-fill when bytes==0 (halo padding).
__device__ __forceinline__ void cp16(uint32_t dst, const void* src, int bytes) {
    asm volatile("cp.async.cg.shared.global [%0], [%1], 16, %2;"
                 :: "r"(dst), "l"(src), "r"(bytes));
}

// packed f32x2 FMA: d.lo = a.lo*b.lo + c.lo ; d.hi = a.hi*b.hi + c.hi  (FFMA2)
__device__ __forceinline__ ull ffma2(ull a, ull b, ull c) {
    ull d;
    asm("fma.rn.f32x2 %0, %1, %2, %3;" : "=l"(d) : "l"(a), "l"(b), "l"(c));
    return d;
}
// cross-pair: returns {hi(a), lo(b)} as packed f32x2
__device__ __forceinline__ ull pk2(ull a, ull b) {
    ull r;
    asm("{\n\t"
        ".reg .b32 ax, ay, bx, by;\n\t"
        "mov.b64 {ax, ay}, %1;\n\t"
        "mov.b64 {bx, by}, %2;\n\t"
        "mov.b64 %0, {ay, bx};\n\t"
        "}" : "=l"(r) : "l"(a), "l"(b));
    return r;
}

__global__ void __launch_bounds__(NTHR, 4)
cost_volume_kernel(const float* __restrict__ left,
                   const float* __restrict__ right,
                   float* __restrict__ out)
{
    __shared__ float smem[SMEM_FLOATS];

    const int tid  = threadIdx.x;
    const int lane = tid & 31;
    const int warp = tid >> 5;          // 0..3
    const int w0   = blockIdx.x * WT;   // 0,128,256 (last tile partial)
    const int h    = blockIdx.y;
    const int n    = blockIdx.z;
    const int d0   = warp * 12;         // disparity group base

    // Rs[i] holds global w = w0-48+i. acc[dj][wi] needs R at smem index
    // ib + (wi - dj + 12), wi-dj+12 in [1,15]; ib multiple of 4 -> float4/double2 LDS.
    const int ib = 4 * lane - d0 + 36;

    const size_t chan_stride = (size_t)HH * WW;
    const float* lrow = left  + (size_t)n * CC * chan_stride + (size_t)h * WW;
    const float* rrow = right + (size_t)n * CC * chan_stride + (size_t)h * WW;

    // ---- async prefetch of one CHS-channel stage into buffer `buf` ----
    auto prefetch = [&](int c0, float* buf) {
        float* Ls = buf;                 // [CHS][WT]
        float* Rs = buf + CHS * WT;      // [CHS][RT]
        const float* lb = lrow + (size_t)c0 * chan_stride;
        const float* rb = rrow + (size_t)c0 * chan_stride;
        // L: CHS*WT/4 = 512 float4, 4 per thread
        #pragma unroll
        for (int it = 0; it < 4; it++) {
            int idx = tid + it * NTHR;       // 0..511
            int c   = idx >> 5;              // /(WT/4)
            int wq  = (idx & 31) << 2;
            int gw  = w0 + wq;
            bool ok = (gw < WW);
            const float* src = ok ? (lb + (size_t)c * chan_stride + gw) : lb;
            cp16(smem_u32(Ls + c * WT + wq), src, ok ? 16 : 0);
        }
        // R: CHS*RT/4 = 704 float4
        #pragma unroll
        for (int it = 0; it < 6; it++) {
            int idx = tid + it * NTHR;
            if (idx < CHS * (RT / 4)) {
                int c  = idx / (RT / 4);
                int wq = (idx - c * (RT / 4)) << 2;
                int gw = w0 - 48 + wq;
                bool ok = (gw >= 0) && (gw < WW);
                const float* src = ok ? (rb + (size_t)c * chan_stride + gw) : rb;
                cp16(smem_u32(Rs + c * RT + wq), src, ok ? 16 : 0);
            }
        }
        asm volatile("cp.async.commit_group;");
    };

    // packed accumulators: acc2[dj][0] = {acc[dj][w0..1]}, acc2[dj][1] = {acc[dj][w2..3]}
    ull acc2[12][2];
    #pragma unroll
    for (int j = 0; j < 12; j++) { acc2[j][0] = 0ull; acc2[j][1] = 0ull; }

    prefetch(0, smem);

    for (int s = 0; s < NSTG; s++) {
        float* cur = smem + (s & 1) * STAGE_FLOATS;
        if (s + 1 < NSTG) {
            prefetch((s + 1) * CHS, smem + ((s + 1) & 1) * STAGE_FLOATS);
            asm volatile("cp.async.wait_group 1;");   // stage s complete
        } else {
            asm volatile("cp.async.wait_group 0;");
        }
        __syncthreads();

        // ---- FFMA2 mainloop: per channel 5 LDS.128 -> 24 packed FMAs (48 flops-lanes) ----
        const float* lp = cur + 4 * lane;
        const float* rp = cur + CHS * WT + ib;
        #pragma unroll 2
        for (int c = 0; c < CHS; c++) {
            // L pairs come free from a double2 view of the float4
            double2 lv = *(const double2*)(lp + c * WT);
            ull lw01 = __double_as_longlong(lv.x);   // {l[w0], l[w1]}
            ull lw23 = __double_as_longlong(lv.y);   // {l[w2], l[w3]}

            // r window: 16 floats as 8 natural (even) pairs
            ull e[8];
            #pragma unroll
            for (int k = 0; k < 4; k++) {
                double2 rv = *(const double2*)(rp + c * RT + 4 * k);
                e[2*k]   = __double_as_longlong(rv.x);
                e[2*k+1] = __double_as_longlong(rv.y);
            }
            // odd-start pairs o[j] = {r[2j+1], r[2j+2]}
            ull o[7];
            #pragma unroll
            for (int j = 0; j < 7; j++) o[j] = pk2(e[j], e[j+1]);

            #pragma unroll
            for (int dj = 0; dj < 12; dj++) {
                const int s0 = 12 - dj;   // b-pair start for wi{0,1}
                const int s1 = 14 - dj;   // b-pair start for wi{2,3}
                ull b0 = (s0 & 1) ? o[(s0 - 1) >> 1] : e[s0 >> 1];
                ull b1 = (s1 & 1) ? o[(s1 - 1) >> 1] : e[s1 >> 1];
                acc2[dj][0] = ffma2(lw01, b0, acc2[dj][0]);
                acc2[dj][1] = ffma2(lw23, b1, acc2[dj][1]);
            }
        }
        __syncthreads();   // compute done before next prefetch overwrites this buffer
    }

    // ---- store: unpack pairs, float4 per disparity row; last tile guarded ----
    const int gw = w0 + 4 * lane;
    if (gw < WW) {
        #pragma unroll
        for (int dj = 0; dj < 12; dj++) {
            int d = d0 + dj;
            float4 v;
            asm("mov.b64 {%0, %1}, %2;" : "=f"(v.x), "=f"(v.y) : "l"(acc2[dj][0]));
            asm("mov.b64 {%0, %1}, %2;" : "=f"(v.z), "=f"(v.w) : "l"(acc2[dj][1]));
            *(float4*)(out + (((size_t)(n * DD + d) * HH + h) * WW + gw)) = v;
        }
    }
}

extern "C" void kernel_launch(void* const* d_in, const int* in_sizes, int n_in,
                              void* d_out, int out_size)
{
    const float* left  = (const float*)d_in[0];
    const float* right = (const float*)d_in[1];
    float* out = (float*)d_out;

    dim3 grid((WW + WT - 1) / WT, HH, NB);   // (3, 160, 4)
    cost_volume_kernel<<<grid, NTHR>>>(left, right, out);
}